// round 15
// baseline (speedup 1.0000x reference)
#include <cuda_runtime.h>
#include <cuda_fp16.h>
#include <cstdint>
#include <cstdio>

#define NN 100000
#define NE 1600000
#define SCAN_B 391          // ceil(NN/256)
#define NSPLIT 50048        // partition boundary (391 * 128)

// ---------------- scratch ----------------------------------------------------
__device__ int    g_is64;
__device__ int    g_esrc[NE];
__device__ int    g_edst[NE];
__device__ int    g_cnt[NN];
__device__ int    g_off[NN];
__device__ int    g_cur[NN];
__device__ int    g_src[NE];
__device__ int    g_eid[NE];
__device__ int    g_bsum[SCAN_B];
__device__ int    g_bpre[SCAN_B];
__device__ __half g_yh[(size_t)NN * 256];   // gathered: y1, then u (y1 dead after agg1)
__device__ __half g_y2[(size_t)NN * 128];   // gathered: y2 (separate: WAR vs agg1 gathers)
__device__ __half g_rh[(size_t)NN * 256];   // streamed: r1 / r2 / v (row-partition-local)
__device__ __half g_hh[(size_t)NN * 256];   // h
__device__ __half g_zh[(size_t)NN * 128];   // z
__device__ __half g_w1[512 * 256];          // [W1l; W1r]
__device__ __half g_w2[256 * 256];          // [W2l; W2r]
__device__ __half g_wd[256 * 128];          // [Wd1_A; Wd1_B]

// ---------------- side stream + events for pipelining -------------------------
struct SideStream {
    cudaStream_t s = nullptr;
    cudaEvent_t ev[8] = {};
    SideStream() {
        cudaStreamCreateWithFlags(&s, cudaStreamNonBlocking);
        for (int i = 0; i < 8; i++)
            cudaEventCreateWithFlags(&ev[i], cudaEventDisableTiming);
    }
};
static SideStream g_ss;

// ---------------- helpers ----------------------------------------------------
__device__ __forceinline__ uint32_t h2u(float x, float y) {
    __half2 h = __floats2half2_rn(x, y);
    return *reinterpret_cast<uint32_t*>(&h);
}
__device__ __forceinline__ float2 u2f(uint32_t u) {
    __half2 h = *reinterpret_cast<__half2*>(&u);
    return __half22float2(h);
}

__device__ __forceinline__ void mma_f16(float4& c, uint32_t a0, uint32_t a1,
                                        uint32_t a2, uint32_t a3,
                                        uint32_t b0, uint32_t b1) {
    asm volatile(
        "mma.sync.aligned.m16n8k16.row.col.f32.f16.f16.f32 "
        "{%0,%1,%2,%3}, {%4,%5,%6,%7}, {%8,%9}, {%0,%1,%2,%3};"
        : "+f"(c.x), "+f"(c.y), "+f"(c.z), "+f"(c.w)
        : "r"(a0), "r"(a1), "r"(a2), "r"(a3), "r"(b0), "r"(b1));
}

__device__ __forceinline__ void ldsm_x4(uint32_t& r0, uint32_t& r1,
                                        uint32_t& r2, uint32_t& r3, uint32_t addr) {
    asm volatile("ldmatrix.sync.aligned.m8n8.x4.shared.b16 {%0,%1,%2,%3}, [%4];"
        : "=r"(r0), "=r"(r1), "=r"(r2), "=r"(r3) : "r"(addr));
}

__device__ __forceinline__ void cp_async16(uint32_t dst, const void* src, bool pred) {
    int sz = pred ? 16 : 0;
    asm volatile("cp.async.cg.shared.global [%0], [%1], 16, %2;"
        :: "r"(dst), "l"(src), "r"(sz) : "memory");
}
#define CP_COMMIT() asm volatile("cp.async.commit_group;" ::: "memory")
#define CP_WAIT(n)  asm volatile("cp.async.wait_group %0;" :: "n"(n) : "memory")

// ---------------- weight pre-conversion to fp16 ------------------------------
__global__ void k_cvtW(const float* __restrict__ W1l, const float* __restrict__ W1r,
                       const float* __restrict__ W2l, const float* __restrict__ W2r,
                       const float* __restrict__ Wd1) {
    int idx = blockIdx.x * blockDim.x + threadIdx.x;
    if (idx < 512 * 256) {
        int row = idx >> 8, col = idx & 255;
        float v = (row < 256) ? W1l[row * 256 + col] : W1r[(row - 256) * 256 + col];
        g_w1[idx] = __float2half_rn(v);
    } else if (idx < 512 * 256 + 256 * 256) {
        int j = idx - 512 * 256;
        int row = j >> 8, col = j & 255;
        float v = (row < 128) ? W2l[row * 256 + col] : W2r[(row - 128) * 256 + col];
        g_w2[j] = __float2half_rn(v);
    } else if (idx < 512 * 256 + 256 * 256 + 256 * 128) {
        int j = idx - 512 * 256 - 256 * 256;
        int row = j >> 7, col = j & 127;
        float v = Wd1[(row & 127) * 256 + (row >> 7) * 128 + col];
        g_wd[j] = __float2half_rn(v);
    }
}

// ---------------- edge index dtype detection + normalization ----------------
__global__ void k_detect(const int* __restrict__ p) {
    if (threadIdx.x == 0 && blockIdx.x == 0) {
        int odd_nonzero = 0;
        for (int i = 0; i < 1024; i++) {
            if (p[2 * i + 1] != 0) { odd_nonzero = 1; break; }
        }
        g_is64 = odd_nonzero ? 0 : 1;
    }
}

__global__ void k_cvt_hist(const void* __restrict__ ei) {
    int e = blockIdx.x * blockDim.x + threadIdx.x;
    if (e >= NE) return;
    int s, d;
    if (g_is64) {
        const long long* p = (const long long*)ei;
        s = (int)p[e];
        d = (int)p[NE + e];
    } else {
        const int* p = (const int*)ei;
        s = p[e];
        d = p[NE + e];
    }
    g_esrc[e] = s;
    g_edst[e] = d;
    atomicAdd(&g_cnt[d], 1);
}

__global__ void k_zero_cnt() {
    int i = blockIdx.x * blockDim.x + threadIdx.x;
    if (i < NN) g_cnt[i] = 0;
}

// ---------------- multi-block exclusive scan (3 phases) ----------------------
__global__ void k_scanA() {
    int i = blockIdx.x * 256 + threadIdx.x;
    int v = (i < NN) ? g_cnt[i] : 0;
    int lane = threadIdx.x & 31;
    int wid = threadIdx.x >> 5;
#pragma unroll
    for (int off = 16; off > 0; off >>= 1)
        v += __shfl_xor_sync(0xFFFFFFFFu, v, off);
    __shared__ int ws[8];
    if (lane == 0) ws[wid] = v;
    __syncthreads();
    if (threadIdx.x == 0) {
        int s = 0;
#pragma unroll
        for (int w = 0; w < 8; w++) s += ws[w];
        g_bsum[blockIdx.x] = s;
    }
}

__global__ void k_scanB() {
    __shared__ int ws[16];
    const int t = threadIdx.x;           // 512 threads
    int v = (t < SCAN_B) ? g_bsum[t] : 0;
    int lane = t & 31, wid = t >> 5;
    int x = v;
#pragma unroll
    for (int off = 1; off < 32; off <<= 1) {
        int y = __shfl_up_sync(0xFFFFFFFFu, x, off);
        if (lane >= off) x += y;
    }
    if (lane == 31) ws[wid] = x;
    __syncthreads();
    int base = 0;
    for (int w = 0; w < wid; w++) base += ws[w];
    if (t < SCAN_B) g_bpre[t] = base + x - v;   // exclusive prefix
}

__global__ void k_scanC() {
    __shared__ int ws[8];
    int i = blockIdx.x * 256 + threadIdx.x;
    int v = (i < NN) ? g_cnt[i] : 0;
    int lane = threadIdx.x & 31, wid = threadIdx.x >> 5;
    int x = v;
#pragma unroll
    for (int off = 1; off < 32; off <<= 1) {
        int y = __shfl_up_sync(0xFFFFFFFFu, x, off);
        if (lane >= off) x += y;
    }
    if (lane == 31) ws[wid] = x;
    __syncthreads();
    int base = g_bpre[blockIdx.x];
    for (int w = 0; w < wid; w++) base += ws[w];
    if (i < NN) {
        int off = base + x - v;
        g_off[i] = off;
        g_cur[i] = off;
    }
}

__global__ void k_scatter() {
    int e = blockIdx.x * blockDim.x + threadIdx.x;
    if (e < NE) {
        int pos = atomicAdd(&g_cur[g_edst[e]], 1);
        g_src[pos] = g_esrc[e];
        g_eid[pos] = e;
    }
}

// ---------------- fused dual-GEMM: mma.sync fp16 + ldmatrix + cp.async -------
template <int K, int NBLK, bool AF16>
__global__ void __launch_bounds__(256, 2)
k_gemm_mma(const void* __restrict__ A, const __half* __restrict__ W,
           __half* __restrict__ Cl, __half* __restrict__ Cr, int M, int NHALF,
           int bm0) {
    constexpr int SA = K / 2 + 4;
    constexpr int SW = 20;
    constexpr int NCHK = K / 32;
    constexpr int WSTAGE_W = 128 * SW;
    extern __shared__ uint32_t smem[];
    uint32_t* Asm = smem;
    uint32_t* Wsm = smem + 128 * SA;

    const int tid = threadIdx.x;
    const int wid = tid >> 5;
    const int lane = tid & 31;
    const int wm = wid >> 2;
    const int wn = wid & 3;
    const int qr = lane >> 2;
    const int tig = lane & 3;
    const int bm = bm0 + blockIdx.x * 128;

    const uint32_t asm_base = (uint32_t)__cvta_generic_to_shared(Asm);
    const uint32_t wsm_base = (uint32_t)__cvta_generic_to_shared(Wsm);

    auto issue_w = [&](const __half* Wp, int c, int s) {
#pragma unroll
        for (int r = 0; r < 2; r++) {
            int p = tid + r * 256;
            int row = p >> 2, seg = p & 3;
            cp_async16(wsm_base + (uint32_t)((s * WSTAGE_W + row * SW + seg * 4) << 2),
                       Wp + (size_t)row * K + c * 32 + seg * 8, true);
        }
    };

    if (AF16) {
        const __half* Ah = (const __half*)A;
        constexpr int SEGS = K / 8;
#pragma unroll
        for (int r = 0; r < (128 * SEGS) / 256; r++) {
            int p = tid + r * 256;
            int row = p / SEGS, seg = p % SEGS;
            cp_async16(asm_base + (uint32_t)((row * SA + seg * 4) << 2),
                       Ah + (size_t)(bm + row) * K + seg * 8, bm + row < M);
        }
        CP_COMMIT();
        for (int s = 0; s < 3; s++) { issue_w(W, s, s); CP_COMMIT(); }
    } else {
        for (int s = 0; s < 3; s++) { issue_w(W, s, s); CP_COMMIT(); }
        const float* Af = (const float*)A;
        for (int it = tid; it < 128 * (K / 16); it += 256) {
            int row = it / (K / 16);
            int g = it % (K / 16);
            uint32_t w[8];
#pragma unroll
            for (int q = 0; q < 4; q++) {
                float4 f = make_float4(0.f, 0.f, 0.f, 0.f);
                if (bm + row < M)
                    f = __ldcs(reinterpret_cast<const float4*>(
                        &Af[(size_t)(bm + row) * K + g * 16 + q * 4]));
                w[2 * q]     = h2u(f.x, f.y);
                w[2 * q + 1] = h2u(f.z, f.w);
            }
            uint32_t* dst = &Asm[row * SA + g * 8];
            *reinterpret_cast<uint4*>(dst)     = make_uint4(w[0], w[1], w[2], w[3]);
            *reinterpret_cast<uint4*>(dst + 4) = make_uint4(w[4], w[5], w[6], w[7]);
        }
    }

    const int rowA = (lane & 7) | (((lane >> 3) & 1) << 3);
    const int kwA = ((lane >> 4) & 1) * 4;
    uint32_t aAddr[4];
#pragma unroll
    for (int mt = 0; mt < 4; mt++)
        aAddr[mt] = asm_base + (((wm * 64 + mt * 16 + rowA) * SA + kwA) << 2);
    const int rowB = (lane & 7) + (((lane >> 4) & 1) << 3);
    const int kwB = ((lane >> 3) & 1) * 4;
    uint32_t bAddr[2];
#pragma unroll
    for (int p = 0; p < 2; p++)
        bAddr[p] = wsm_base + (((wn * 32 + p * 16 + rowB) * SW + kwB) << 2);

    for (int nb = 0; nb < NBLK; nb++) {
        const __half* Wp = W + (size_t)nb * 128 * K;
        const bool isL = (nb * 128 < NHALF);
        const int colbase = isL ? nb * 128 : nb * 128 - NHALF;
        __half* Cp = isL ? Cl : Cr;

        if (nb > 0) {
            for (int s = 0; s < 3; s++) { issue_w(Wp, s, s); CP_COMMIT(); }
        }

        float4 acc[4][4];
#pragma unroll
        for (int i = 0; i < 4; i++)
#pragma unroll
            for (int j = 0; j < 4; j++) acc[i][j] = make_float4(0.f, 0.f, 0.f, 0.f);

        for (int c = 0; c < NCHK; c++) {
            CP_WAIT(2);
            __syncthreads();
            if (c + 3 < NCHK) issue_w(Wp, c + 3, (c + 3) & 3);
            CP_COMMIT();

            const uint32_t wbuf = (uint32_t)(((c & 3) * WSTAGE_W) << 2);
#pragma unroll
            for (int g2 = 0; g2 < 2; g2++) {
                const uint32_t koff = (uint32_t)((c * 16 + g2 * 8) << 2);
                uint32_t a[4][4];
#pragma unroll
                for (int mt = 0; mt < 4; mt++)
                    ldsm_x4(a[mt][0], a[mt][1], a[mt][2], a[mt][3], aAddr[mt] + koff);
                uint32_t b[2][4];
#pragma unroll
                for (int p = 0; p < 2; p++)
                    ldsm_x4(b[p][0], b[p][1], b[p][2], b[p][3],
                            bAddr[p] + wbuf + (uint32_t)((g2 * 8) << 2));
#pragma unroll
                for (int mt = 0; mt < 4; mt++) {
#pragma unroll
                    for (int p = 0; p < 2; p++) {
                        mma_f16(acc[mt][2 * p], a[mt][0], a[mt][1], a[mt][2], a[mt][3],
                                b[p][0], b[p][1]);
                        mma_f16(acc[mt][2 * p + 1], a[mt][0], a[mt][1], a[mt][2], a[mt][3],
                                b[p][2], b[p][3]);
                    }
                }
            }
        }

#pragma unroll
        for (int mt = 0; mt < 4; mt++) {
            int row = bm + wm * 64 + mt * 16 + qr;
#pragma unroll
            for (int nt = 0; nt < 4; nt++) {
                int col = colbase + wn * 32 + nt * 8 + 2 * tig;
                uint32_t lo = h2u(acc[mt][nt].x, acc[mt][nt].y);
                uint32_t hi = h2u(acc[mt][nt].z, acc[mt][nt].w);
                if (isL) {
                    if (row < M)
                        *reinterpret_cast<uint32_t*>(&Cp[(size_t)row * NHALF + col]) = lo;
                    if (row + 8 < M)
                        *reinterpret_cast<uint32_t*>(&Cp[(size_t)(row + 8) * NHALF + col]) = hi;
                } else {
                    if (row < M)
                        __stcs(reinterpret_cast<unsigned int*>(&Cp[(size_t)row * NHALF + col]), lo);
                    if (row + 8 < M)
                        __stcs(reinterpret_cast<unsigned int*>(&Cp[(size_t)(row + 8) * NHALF + col]), hi);
                }
            }
        }
        __syncthreads();
    }
}

// ---------------- aggregation + epilogue (node range [n0, n1)) ---------------
template <int HL, bool RELU>
__global__ void k_agg_h(const __half* __restrict__ y, const __half* __restrict__ r,
                        const float* __restrict__ bias, __half* __restrict__ outp,
                        int n0, int n1) {
    int warp = n0 + ((blockIdx.x * blockDim.x + threadIdx.x) >> 5);
    int lane = threadIdx.x & 31;
    if (warp >= n1) return;
    const int n = warp;
    const int F = 32 * HL;
    int beg = g_off[n];
    int c = g_cnt[n];
    const int fo = lane * HL;

    float a0[HL], a1[HL];
#pragma unroll
    for (int q = 0; q < HL; q++) { a0[q] = 0.f; a1[q] = 0.f; }

    auto loadrow = [&](int s, uint32_t* t) {
        if (HL == 8)
            *reinterpret_cast<uint4*>(t) = *reinterpret_cast<const uint4*>(&y[(size_t)s * F + fo]);
        else
            *reinterpret_cast<uint2*>(t) = *reinterpret_cast<const uint2*>(&y[(size_t)s * F + fo]);
    };
    auto accum = [&](const uint32_t* t, float* a) {
#pragma unroll
        for (int q = 0; q < HL / 2; q++) {
            float2 f = u2f(t[q]);
            a[2 * q] += f.x; a[2 * q + 1] += f.y;
        }
    };

    int i = 0;
    for (; i + 4 <= c; i += 4) {
        int s0 = g_src[beg + i],     s1 = g_src[beg + i + 1];
        int s2 = g_src[beg + i + 2], s3 = g_src[beg + i + 3];
        uint32_t t0[HL / 2], t1[HL / 2], t2[HL / 2], t3[HL / 2];
        loadrow(s0, t0); loadrow(s1, t1); loadrow(s2, t2); loadrow(s3, t3);
        accum(t0, a0); accum(t1, a1); accum(t2, a0); accum(t3, a1);
    }
    for (; i < c; i++) {
        int s = g_src[beg + i];
        uint32_t t[HL / 2];
        loadrow(s, t);
        accum(t, a0);
    }

    float inv = 1.f / (float)(c > 0 ? c : 1);
    uint32_t rw[HL / 2], ow[HL / 2];
    if (HL == 8)
        *reinterpret_cast<uint4*>(rw) = __ldcs(reinterpret_cast<const uint4*>(&r[(size_t)n * F + fo]));
    else
        *reinterpret_cast<uint2*>(rw) = __ldcs(reinterpret_cast<const uint2*>(&r[(size_t)n * F + fo]));
#pragma unroll
    for (int q = 0; q < HL / 2; q++) {
        float2 rr = u2f(rw[q]);
        float bx = bias[fo + 2 * q];
        float by = bias[fo + 2 * q + 1];
        float ox = (a0[2 * q] + a1[2 * q]) * inv + bx + rr.x;
        float oy = (a0[2 * q + 1] + a1[2 * q + 1]) * inv + by + rr.y;
        if (RELU) { ox = fmaxf(ox, 0.f); oy = fmaxf(oy, 0.f); }
        ow[q] = h2u(ox, oy);
    }
    if (HL == 8)
        __stcs(reinterpret_cast<uint4*>(&outp[(size_t)n * F + fo]), *reinterpret_cast<uint4*>(ow));
    else
        __stcs(reinterpret_cast<uint2*>(&outp[(size_t)n * F + fo]), *reinterpret_cast<uint2*>(ow));
}

// ---------------- edge decoder (CSR-grouped; 8 edges in flight per warp) -----
__global__ void k_edge_csr(const __half* __restrict__ u_, const __half* __restrict__ v_,
                           const float* __restrict__ bd1, const float* __restrict__ wd2,
                           const float* __restrict__ bd2, float* __restrict__ out) {
    int warp = (blockIdx.x * blockDim.x + threadIdx.x) >> 5;
    int lane = threadIdx.x & 31;
    if (warp >= NN) return;
    const int n = warp;
    int beg = g_off[n];
    int c = g_cnt[n];
    if (c == 0) return;

    const int sub = lane >> 3;   // edge slot 0..3
    const int fl = lane & 7;     // feature block: cols fl*16 .. fl*16+15

    float w16[16], vb16[16];
#pragma unroll
    for (int q = 0; q < 4; q++) {
        float4 wv = *reinterpret_cast<const float4*>(&wd2[fl * 16 + q * 4]);
        w16[4 * q + 0] = wv.x; w16[4 * q + 1] = wv.y;
        w16[4 * q + 2] = wv.z; w16[4 * q + 3] = wv.w;
        float4 bv = *reinterpret_cast<const float4*>(&bd1[fl * 16 + q * 4]);
        vb16[4 * q + 0] = bv.x; vb16[4 * q + 1] = bv.y;
        vb16[4 * q + 2] = bv.z; vb16[4 * q + 3] = bv.w;
    }
    {
        uint4 vv0 = __ldcs(reinterpret_cast<const uint4*>(&v_[(size_t)n * 128 + fl * 16]));
        uint4 vv1 = __ldcs(reinterpret_cast<const uint4*>(&v_[(size_t)n * 128 + fl * 16 + 8]));
        uint32_t vw[8] = {vv0.x, vv0.y, vv0.z, vv0.w, vv1.x, vv1.y, vv1.z, vv1.w};
#pragma unroll
        for (int q = 0; q < 8; q++) {
            float2 f = u2f(vw[q]);
            vb16[2 * q] += f.x;
            vb16[2 * q + 1] += f.y;
        }
    }
    float b2 = *bd2;

    auto edge_dot = [&](int idx) -> float {
        int s = g_src[idx];
        uint4 uu0 = *reinterpret_cast<const uint4*>(&u_[(size_t)s * 128 + fl * 16]);
        uint4 uu1 = *reinterpret_cast<const uint4*>(&u_[(size_t)s * 128 + fl * 16 + 8]);
        uint32_t uw[8] = {uu0.x, uu0.y, uu0.z, uu0.w, uu1.x, uu1.y, uu1.z, uu1.w};
        float sum = 0.f;
#pragma unroll
        for (int q = 0; q < 8; q++) {
            float2 f = u2f(uw[q]);
            float t;
            t = fmaxf(f.x + vb16[2 * q], 0.f);     sum = fmaf(t, w16[2 * q], sum);
            t = fmaxf(f.y + vb16[2 * q + 1], 0.f); sum = fmaf(t, w16[2 * q + 1], sum);
        }
        sum += __shfl_xor_sync(0xFFFFFFFFu, sum, 4);
        sum += __shfl_xor_sync(0xFFFFFFFFu, sum, 2);
        sum += __shfl_xor_sync(0xFFFFFFFFu, sum, 1);
        return sum;
    };

    int i = 0;
    for (; i + 8 <= c; i += 8) {
        int idxA = beg + i + sub, idxB = beg + i + 4 + sub;
        int eidA = g_eid[idxA], eidB = g_eid[idxB];
        float sA = edge_dot(idxA);
        float sB = edge_dot(idxB);
        if (fl == 0) {
            __stcs(&out[eidA], sA + b2);
            __stcs(&out[eidB], sB + b2);
        }
    }
    for (; i < c; i += 4) {
        int j = i + sub;
        bool ok = (j < c);
        int idx = beg + (ok ? j : c - 1);
        int eid = g_eid[idx];
        float s = edge_dot(idx);
        if (fl == 0 && ok) __stcs(&out[eid], s + b2);
    }
}

// ---------------- launch -----------------------------------------------------
extern "C" void kernel_launch(void* const* d_in, const int* in_sizes, int n_in,
                              void* d_out, int out_size) {
    const float* x       = (const float*)d_in[0];
    const void*  ei      = (const void*)d_in[1];
    const float* W1l     = (const float*)d_in[2];
    const float* b1l     = (const float*)d_in[3];
    const float* W1r     = (const float*)d_in[4];
    const float* W2l     = (const float*)d_in[5];
    const float* b2l     = (const float*)d_in[6];
    const float* W2r     = (const float*)d_in[7];
    const float* Wd1     = (const float*)d_in[8];
    const float* bd1     = (const float*)d_in[9];
    const float* Wd2     = (const float*)d_in[10];
    const float* bd2     = (const float*)d_in[11];
    float* out           = (float*)d_out;

    __half *yh, *y2h, *rh, *hh, *zh, *w1, *w2, *wd;
    cudaGetSymbolAddress((void**)&yh, g_yh);
    cudaGetSymbolAddress((void**)&y2h, g_y2);
    cudaGetSymbolAddress((void**)&rh, g_rh);
    cudaGetSymbolAddress((void**)&hh, g_hh);
    cudaGetSymbolAddress((void**)&zh, g_zh);
    cudaGetSymbolAddress((void**)&w1, g_w1);
    cudaGetSymbolAddress((void**)&w2, g_w2);
    cudaGetSymbolAddress((void**)&wd, g_wd);

    const int smemK256 = (128 * (256 / 2 + 4) + 4 * 128 * 20) * 4;  // 108544
    const int smemK128 = (128 * (128 / 2 + 4) + 4 * 128 * 20) * 4;  //  75776
    cudaFuncSetAttribute(k_gemm_mma<256, 4, false>, cudaFuncAttributeMaxDynamicSharedMemorySize, smemK256);
    cudaFuncSetAttribute(k_gemm_mma<256, 2, true>,  cudaFuncAttributeMaxDynamicSharedMemorySize, smemK256);
    cudaFuncSetAttribute(k_gemm_mma<128, 2, true>,  cudaFuncAttributeMaxDynamicSharedMemorySize, smemK128);

    const int MT = (NN + 127) / 128;               // 782 (full)
    const int MT0 = NSPLIT / 128;                  // 391 (P0 rows)
    const int MT1 = MT - MT0;                      // 391 (P1 rows)
    const int AGG0 = (NSPLIT * 32 + 255) / 256;
    const int AGG1 = ((NN - NSPLIT) * 32 + 255) / 256;
    const int AGGF = (NN * 32 + 255) / 256;

    cudaStream_t s2 = g_ss.s;
    cudaEvent_t* ev = g_ss.ev;
    // ev[0]=fork ev[1]=CSR done ev[2]=agg1 P0 ev[3]=agg1 P1
    // ev[4]=GEMM2 done ev[5]=agg2 P0 ev[6]=agg2 P1 ev[7]=GEMM3 done

    // ---- fork: CSR build on side stream ----
    cudaEventRecord(ev[0], 0);
    cudaStreamWaitEvent(s2, ev[0], 0);
    k_detect<<<1, 32, 0, s2>>>((const int*)ei);
    k_zero_cnt<<<(NN + 255) / 256, 256, 0, s2>>>();
    k_cvt_hist<<<(NE + 255) / 256, 256, 0, s2>>>(ei);
    k_scanA<<<SCAN_B, 256, 0, s2>>>();
    k_scanB<<<1, 512, 0, s2>>>();
    k_scanC<<<SCAN_B, 256, 0, s2>>>();
    k_scatter<<<(NE + 255) / 256, 256, 0, s2>>>();
    cudaEventRecord(ev[1], s2);

    // main: weights + conv1 GEMM (all rows); y1 -> g_yh, r1 -> rh
    k_cvtW<<<(512 * 256 + 256 * 256 + 256 * 128 + 255) / 256, 256>>>(W1l, W1r, W2l, W2r, Wd1);
    k_gemm_mma<256, 4, false><<<MT, 256, smemK256>>>(x, w1, yh, rh, NN, 256, 0);

    // join CSR, then pipelined agg1 -> GEMM2 by partition.
    // GEMM2 writes y2 into g_y2 (NOT g_yh) so agg1(P1)'s global gathers of y1
    // are not clobbered (WAR hazard fixed).
    cudaStreamWaitEvent(0, ev[1], 0);
    k_agg_h<8, true><<<AGG0, 256>>>(yh, rh, b1l, hh, 0, NSPLIT);
    cudaEventRecord(ev[2], 0);
    k_agg_h<8, true><<<AGG1, 256>>>(yh, rh, b1l, hh, NSPLIT, NN);
    cudaEventRecord(ev[3], 0);

    cudaStreamWaitEvent(s2, ev[2], 0);
    k_gemm_mma<256, 2, true><<<MT0, 256, smemK256, s2>>>(hh, w2, y2h, rh, NN, 128, 0);
    cudaStreamWaitEvent(s2, ev[3], 0);
    k_gemm_mma<256, 2, true><<<MT1, 256, smemK256, s2>>>(hh, w2, y2h, rh, NN, 128, NSPLIT);
    cudaEventRecord(ev[4], s2);

    // agg2 gathers y2 from g_y2; GEMM3 writes u into g_yh (y1 dead after agg1).
    cudaStreamWaitEvent(0, ev[4], 0);
    k_agg_h<4, false><<<AGG0, 256>>>(y2h, rh, b2l, zh, 0, NSPLIT);
    cudaEventRecord(ev[5], 0);
    k_agg_h<4, false><<<AGG1, 256>>>(y2h, rh, b2l, zh, NSPLIT, NN);
    cudaEventRecord(ev[6], 0);

    cudaStreamWaitEvent(s2, ev[5], 0);
    k_gemm_mma<128, 2, true><<<MT0, 256, smemK128, s2>>>(zh, wd, yh, rh, NN, 128, 0);
    cudaStreamWaitEvent(s2, ev[6], 0);
    k_gemm_mma<128, 2, true><<<MT1, 256, smemK128, s2>>>(zh, wd, yh, rh, NN, 128, NSPLIT);
    cudaEventRecord(ev[7], s2);

    // edge decoder (needs all GEMM3): u from g_yh, v from rh
    cudaStreamWaitEvent(0, ev[7], 0);
    k_edge_csr<<<AGGF, 256>>>(yh, rh, bd1, Wd2, bd2, out);
}

// round 16
// speedup vs baseline: 1.0153x; 1.0153x over previous
#include <cuda_runtime.h>
#include <cuda_fp16.h>
#include <cstdint>
#include <cstdio>

#define NN 100000
#define NE 1600000
#define SCAN_B 391          // ceil(NN/256)

// ---------------- scratch ----------------------------------------------------
__device__ int    g_is64;
__device__ int    g_esrc[NE];
__device__ int    g_edst[NE];
__device__ int    g_cnt[NN];
__device__ int    g_off[NN];
__device__ int    g_cur[NN];
__device__ int    g_src[NE];
__device__ int    g_eid[NE];
__device__ int    g_bsum[SCAN_B];
__device__ int    g_bpre[SCAN_B];
__device__ __half g_yh[(size_t)NN * 256];   // gathered: y1 / y2 / u  (keep in L2)
__device__ __half g_rh[(size_t)NN * 256];   // streamed: r1 / r2 / v  (evict-first)
__device__ __half g_hh[(size_t)NN * 256];   // h
__device__ __half g_zh[(size_t)NN * 128];   // z
__device__ __half g_w1[512 * 256];          // [W1l; W1r]
__device__ __half g_w2[256 * 256];          // [W2l; W2r]
__device__ __half g_wd[256 * 128];          // [Wd1_A; Wd1_B]

// ---------------- side stream for CSR/GEMM overlap ---------------------------
struct SideStream {
    cudaStream_t s = nullptr;
    cudaEvent_t fork = nullptr, join = nullptr;
    SideStream() {
        cudaStreamCreateWithFlags(&s, cudaStreamNonBlocking);
        cudaEventCreateWithFlags(&fork, cudaEventDisableTiming);
        cudaEventCreateWithFlags(&join, cudaEventDisableTiming);
    }
};
static SideStream g_ss;

// ---------------- helpers ----------------------------------------------------
__device__ __forceinline__ uint32_t h2u(float x, float y) {
    __half2 h = __floats2half2_rn(x, y);
    return *reinterpret_cast<uint32_t*>(&h);
}
__device__ __forceinline__ float2 u2f(uint32_t u) {
    __half2 h = *reinterpret_cast<__half2*>(&u);
    return __half22float2(h);
}

__device__ __forceinline__ void mma_f16(float4& c, uint32_t a0, uint32_t a1,
                                        uint32_t a2, uint32_t a3,
                                        uint32_t b0, uint32_t b1) {
    asm volatile(
        "mma.sync.aligned.m16n8k16.row.col.f32.f16.f16.f32 "
        "{%0,%1,%2,%3}, {%4,%5,%6,%7}, {%8,%9}, {%0,%1,%2,%3};"
        : "+f"(c.x), "+f"(c.y), "+f"(c.z), "+f"(c.w)
        : "r"(a0), "r"(a1), "r"(a2), "r"(a3), "r"(b0), "r"(b1));
}

__device__ __forceinline__ void ldsm_x4(uint32_t& r0, uint32_t& r1,
                                        uint32_t& r2, uint32_t& r3, uint32_t addr) {
    asm volatile("ldmatrix.sync.aligned.m8n8.x4.shared.b16 {%0,%1,%2,%3}, [%4];"
        : "=r"(r0), "=r"(r1), "=r"(r2), "=r"(r3) : "r"(addr));
}

__device__ __forceinline__ void cp_async16(uint32_t dst, const void* src, bool pred) {
    int sz = pred ? 16 : 0;
    asm volatile("cp.async.cg.shared.global [%0], [%1], 16, %2;"
        :: "r"(dst), "l"(src), "r"(sz) : "memory");
}
#define CP_COMMIT() asm volatile("cp.async.commit_group;" ::: "memory")
#define CP_WAIT(n)  asm volatile("cp.async.wait_group %0;" :: "n"(n) : "memory")

// ---------------- weight pre-conversion to fp16 ------------------------------
__global__ void k_cvtW(const float* __restrict__ W1l, const float* __restrict__ W1r,
                       const float* __restrict__ W2l, const float* __restrict__ W2r,
                       const float* __restrict__ Wd1) {
    int idx = blockIdx.x * blockDim.x + threadIdx.x;
    if (idx < 512 * 256) {
        int row = idx >> 8, col = idx & 255;
        float v = (row < 256) ? W1l[row * 256 + col] : W1r[(row - 256) * 256 + col];
        g_w1[idx] = __float2half_rn(v);
    } else if (idx < 512 * 256 + 256 * 256) {
        int j = idx - 512 * 256;
        int row = j >> 8, col = j & 255;
        float v = (row < 128) ? W2l[row * 256 + col] : W2r[(row - 128) * 256 + col];
        g_w2[j] = __float2half_rn(v);
    } else if (idx < 512 * 256 + 256 * 256 + 256 * 128) {
        int j = idx - 512 * 256 - 256 * 256;
        int row = j >> 7, col = j & 127;
        float v = Wd1[(row & 127) * 256 + (row >> 7) * 128 + col];
        g_wd[j] = __float2half_rn(v);
    }
}

// ---------------- edge index dtype detection + normalization ----------------
__global__ void k_detect(const int* __restrict__ p) {
    if (threadIdx.x == 0 && blockIdx.x == 0) {
        int odd_nonzero = 0;
        for (int i = 0; i < 1024; i++) {
            if (p[2 * i + 1] != 0) { odd_nonzero = 1; break; }
        }
        g_is64 = odd_nonzero ? 0 : 1;
    }
}

__global__ void k_cvt_hist(const void* __restrict__ ei) {
    int e = blockIdx.x * blockDim.x + threadIdx.x;
    if (e >= NE) return;
    int s, d;
    if (g_is64) {
        const long long* p = (const long long*)ei;
        s = (int)p[e];
        d = (int)p[NE + e];
    } else {
        const int* p = (const int*)ei;
        s = p[e];
        d = p[NE + e];
    }
    g_esrc[e] = s;
    g_edst[e] = d;
    atomicAdd(&g_cnt[d], 1);
}

__global__ void k_zero_cnt() {
    int i = blockIdx.x * blockDim.x + threadIdx.x;
    if (i < NN) g_cnt[i] = 0;
}

// ---------------- multi-block exclusive scan (3 phases) ----------------------
__global__ void k_scanA() {
    int i = blockIdx.x * 256 + threadIdx.x;
    int v = (i < NN) ? g_cnt[i] : 0;
    int lane = threadIdx.x & 31;
    int wid = threadIdx.x >> 5;
#pragma unroll
    for (int off = 16; off > 0; off >>= 1)
        v += __shfl_xor_sync(0xFFFFFFFFu, v, off);
    __shared__ int ws[8];
    if (lane == 0) ws[wid] = v;
    __syncthreads();
    if (threadIdx.x == 0) {
        int s = 0;
#pragma unroll
        for (int w = 0; w < 8; w++) s += ws[w];
        g_bsum[blockIdx.x] = s;
    }
}

__global__ void k_scanB() {
    __shared__ int ws[16];
    const int t = threadIdx.x;           // 512 threads
    int v = (t < SCAN_B) ? g_bsum[t] : 0;
    int lane = t & 31, wid = t >> 5;
    int x = v;
#pragma unroll
    for (int off = 1; off < 32; off <<= 1) {
        int y = __shfl_up_sync(0xFFFFFFFFu, x, off);
        if (lane >= off) x += y;
    }
    if (lane == 31) ws[wid] = x;
    __syncthreads();
    int base = 0;
    for (int w = 0; w < wid; w++) base += ws[w];
    if (t < SCAN_B) g_bpre[t] = base + x - v;   // exclusive prefix
}

__global__ void k_scanC() {
    __shared__ int ws[8];
    int i = blockIdx.x * 256 + threadIdx.x;
    int v = (i < NN) ? g_cnt[i] : 0;
    int lane = threadIdx.x & 31, wid = threadIdx.x >> 5;
    int x = v;
#pragma unroll
    for (int off = 1; off < 32; off <<= 1) {
        int y = __shfl_up_sync(0xFFFFFFFFu, x, off);
        if (lane >= off) x += y;
    }
    if (lane == 31) ws[wid] = x;
    __syncthreads();
    int base = g_bpre[blockIdx.x];
    for (int w = 0; w < wid; w++) base += ws[w];
    if (i < NN) {
        int off = base + x - v;
        g_off[i] = off;
        g_cur[i] = off;
    }
}

__global__ void k_scatter() {
    int e = blockIdx.x * blockDim.x + threadIdx.x;
    if (e < NE) {
        int pos = atomicAdd(&g_cur[g_edst[e]], 1);
        g_src[pos] = g_esrc[e];
        g_eid[pos] = e;
    }
}

// ---------------- fused dual-GEMM, M=256 per CTA (2 A-tiles share W stream) --
// C[M, NTOT] = A[M,K] @ W[NTOT,K]^T, NTOT = NBLK*128, W fp16 stacked.
// Two 128-row A tiles resident in SMEM; every streamed W chunk feeds both
// (B fragments loaded once per k-group) -> W L2 traffic halves.
template <int K, int NBLK, bool AF16>
__global__ void __launch_bounds__(256, 1)
k_gemm_mma(const void* __restrict__ A, const __half* __restrict__ W,
           __half* __restrict__ Cl, __half* __restrict__ Cr, int M, int NHALF) {
    constexpr int SA = K / 2 + 4;       // A row stride (32-bit words)
    constexpr int SW = 20;              // W row stride (words)
    constexpr int NCHK = K / 32;        // K chunks
    constexpr int WSTAGE_W = 128 * SW;  // words per W stage
    extern __shared__ uint32_t smem[];
    uint32_t* Asm = smem;                        // 256 rows * SA (two tiles)
    uint32_t* Wsm = smem + 256 * SA;             // 4 * WSTAGE_W

    const int tid = threadIdx.x;
    const int wid = tid >> 5;
    const int lane = tid & 31;
    const int wm = wid >> 2;
    const int wn = wid & 3;
    const int qr = lane >> 2;
    const int tig = lane & 3;
    const int bm = blockIdx.x * 256;

    const uint32_t asm_base = (uint32_t)__cvta_generic_to_shared(Asm);
    const uint32_t wsm_base = (uint32_t)__cvta_generic_to_shared(Wsm);

    auto issue_w = [&](const __half* Wp, int c, int s) {
#pragma unroll
        for (int r = 0; r < 2; r++) {
            int p = tid + r * 256;
            int row = p >> 2, seg = p & 3;
            cp_async16(wsm_base + (uint32_t)((s * WSTAGE_W + row * SW + seg * 4) << 2),
                       Wp + (size_t)row * K + c * 32 + seg * 8, true);
        }
    };

    // ---- A tile load: 256 rows ----
    if (AF16) {
        const __half* Ah = (const __half*)A;
        constexpr int SEGS = K / 8;
#pragma unroll
        for (int r = 0; r < (256 * SEGS) / 256; r++) {
            int p = tid + r * 256;
            int row = p / SEGS, seg = p % SEGS;
            cp_async16(asm_base + (uint32_t)((row * SA + seg * 4) << 2),
                       Ah + (size_t)(bm + row) * K + seg * 8, bm + row < M);
        }
        CP_COMMIT();
        for (int s = 0; s < 3; s++) { issue_w(W, s, s); CP_COMMIT(); }
    } else {
        for (int s = 0; s < 3; s++) { issue_w(W, s, s); CP_COMMIT(); }
        const float* Af = (const float*)A;
        for (int it = tid; it < 256 * (K / 16); it += 256) {
            int row = it / (K / 16);
            int g = it % (K / 16);
            uint32_t w[8];
#pragma unroll
            for (int q = 0; q < 4; q++) {
                float4 f = make_float4(0.f, 0.f, 0.f, 0.f);
                if (bm + row < M)
                    f = __ldcs(reinterpret_cast<const float4*>(
                        &Af[(size_t)(bm + row) * K + g * 16 + q * 4]));
                w[2 * q]     = h2u(f.x, f.y);
                w[2 * q + 1] = h2u(f.z, f.w);
            }
            uint32_t* dst = &Asm[row * SA + g * 8];
            *reinterpret_cast<uint4*>(dst)     = make_uint4(w[0], w[1], w[2], w[3]);
            *reinterpret_cast<uint4*>(dst + 4) = make_uint4(w[4], w[5], w[6], w[7]);
        }
    }

    // ldmatrix per-lane addresses (two A tiles)
    const int rowA = (lane & 7) | (((lane >> 3) & 1) << 3);
    const int kwA = ((lane >> 4) & 1) * 4;
    uint32_t aAddr[2][4];
#pragma unroll
    for (int t = 0; t < 2; t++)
#pragma unroll
        for (int mt = 0; mt < 4; mt++)
            aAddr[t][mt] = asm_base +
                (((t * 128 + wm * 64 + mt * 16 + rowA) * SA + kwA) << 2);
    const int rowB = (lane & 7) + (((lane >> 4) & 1) << 3);
    const int kwB = ((lane >> 3) & 1) * 4;
    uint32_t bAddr[2];
#pragma unroll
    for (int p = 0; p < 2; p++)
        bAddr[p] = wsm_base + (((wn * 32 + p * 16 + rowB) * SW + kwB) << 2);

    for (int nb = 0; nb < NBLK; nb++) {
        const __half* Wp = W + (size_t)nb * 128 * K;
        const bool isL = (nb * 128 < NHALF);
        const int colbase = isL ? nb * 128 : nb * 128 - NHALF;
        __half* Cp = isL ? Cl : Cr;

        if (nb > 0) {
            for (int s = 0; s < 3; s++) { issue_w(Wp, s, s); CP_COMMIT(); }
        }

        float4 acc[2][4][4];
#pragma unroll
        for (int t = 0; t < 2; t++)
#pragma unroll
            for (int i = 0; i < 4; i++)
#pragma unroll
                for (int j = 0; j < 4; j++)
                    acc[t][i][j] = make_float4(0.f, 0.f, 0.f, 0.f);

        for (int c = 0; c < NCHK; c++) {
            CP_WAIT(2);
            __syncthreads();
            if (c + 3 < NCHK) issue_w(Wp, c + 3, (c + 3) & 3);
            CP_COMMIT();

            const uint32_t wbuf = (uint32_t)(((c & 3) * WSTAGE_W) << 2);
#pragma unroll
            for (int g2 = 0; g2 < 2; g2++) {
                const uint32_t koff = (uint32_t)((c * 16 + g2 * 8) << 2);
                uint32_t b[2][4];
#pragma unroll
                for (int p = 0; p < 2; p++)
                    ldsm_x4(b[p][0], b[p][1], b[p][2], b[p][3],
                            bAddr[p] + wbuf + (uint32_t)((g2 * 8) << 2));
#pragma unroll
                for (int t = 0; t < 2; t++) {
                    uint32_t a[4][4];
#pragma unroll
                    for (int mt = 0; mt < 4; mt++)
                        ldsm_x4(a[mt][0], a[mt][1], a[mt][2], a[mt][3],
                                aAddr[t][mt] + koff);
#pragma unroll
                    for (int mt = 0; mt < 4; mt++) {
#pragma unroll
                        for (int p = 0; p < 2; p++) {
                            mma_f16(acc[t][mt][2 * p], a[mt][0], a[mt][1], a[mt][2], a[mt][3],
                                    b[p][0], b[p][1]);
                            mma_f16(acc[t][mt][2 * p + 1], a[mt][0], a[mt][1], a[mt][2], a[mt][3],
                                    b[p][2], b[p][3]);
                        }
                    }
                }
            }
        }

        // epilogue: Cl normal (gathered next), Cr evict-first (streamed next)
#pragma unroll
        for (int t = 0; t < 2; t++) {
#pragma unroll
            for (int mt = 0; mt < 4; mt++) {
                int row = bm + t * 128 + wm * 64 + mt * 16 + qr;
#pragma unroll
                for (int nt = 0; nt < 4; nt++) {
                    int col = colbase + wn * 32 + nt * 8 + 2 * tig;
                    uint32_t lo = h2u(acc[t][mt][nt].x, acc[t][mt][nt].y);
                    uint32_t hi = h2u(acc[t][mt][nt].z, acc[t][mt][nt].w);
                    if (isL) {
                        if (row < M)
                            *reinterpret_cast<uint32_t*>(&Cp[(size_t)row * NHALF + col]) = lo;
                        if (row + 8 < M)
                            *reinterpret_cast<uint32_t*>(&Cp[(size_t)(row + 8) * NHALF + col]) = hi;
                    } else {
                        if (row < M)
                            __stcs(reinterpret_cast<unsigned int*>(&Cp[(size_t)row * NHALF + col]), lo);
                        if (row + 8 < M)
                            __stcs(reinterpret_cast<unsigned int*>(&Cp[(size_t)(row + 8) * NHALF + col]), hi);
                    }
                }
            }
        }
        __syncthreads();
    }
}

// ---------------- aggregation + epilogue (fp16 in/out, fp32 accumulate) ------
template <int HL, bool RELU>
__global__ void k_agg_h(const __half* __restrict__ y, const __half* __restrict__ r,
                        const float* __restrict__ bias, __half* __restrict__ outp) {
    int warp = (blockIdx.x * blockDim.x + threadIdx.x) >> 5;
    int lane = threadIdx.x & 31;
    if (warp >= NN) return;
    const int n = warp;
    const int F = 32 * HL;
    int beg = g_off[n];
    int c = g_cnt[n];
    const int fo = lane * HL;

    float a0[HL], a1[HL];
#pragma unroll
    for (int q = 0; q < HL; q++) { a0[q] = 0.f; a1[q] = 0.f; }

    auto loadrow = [&](int s, uint32_t* t) {
        if (HL == 8)
            *reinterpret_cast<uint4*>(t) = *reinterpret_cast<const uint4*>(&y[(size_t)s * F + fo]);
        else
            *reinterpret_cast<uint2*>(t) = *reinterpret_cast<const uint2*>(&y[(size_t)s * F + fo]);
    };
    auto accum = [&](const uint32_t* t, float* a) {
#pragma unroll
        for (int q = 0; q < HL / 2; q++) {
            float2 f = u2f(t[q]);
            a[2 * q] += f.x; a[2 * q + 1] += f.y;
        }
    };

    int i = 0;
    for (; i + 4 <= c; i += 4) {
        int s0 = g_src[beg + i],     s1 = g_src[beg + i + 1];
        int s2 = g_src[beg + i + 2], s3 = g_src[beg + i + 3];
        uint32_t t0[HL / 2], t1[HL / 2], t2[HL / 2], t3[HL / 2];
        loadrow(s0, t0); loadrow(s1, t1); loadrow(s2, t2); loadrow(s3, t3);
        accum(t0, a0); accum(t1, a1); accum(t2, a0); accum(t3, a1);
    }
    for (; i < c; i++) {
        int s = g_src[beg + i];
        uint32_t t[HL / 2];
        loadrow(s, t);
        accum(t, a0);
    }

    float inv = 1.f / (float)(c > 0 ? c : 1);
    uint32_t rw[HL / 2], ow[HL / 2];
    if (HL == 8)
        *reinterpret_cast<uint4*>(rw) = __ldcs(reinterpret_cast<const uint4*>(&r[(size_t)n * F + fo]));
    else
        *reinterpret_cast<uint2*>(rw) = __ldcs(reinterpret_cast<const uint2*>(&r[(size_t)n * F + fo]));
#pragma unroll
    for (int q = 0; q < HL / 2; q++) {
        float2 rr = u2f(rw[q]);
        float bx = bias[fo + 2 * q];
        float by = bias[fo + 2 * q + 1];
        float ox = (a0[2 * q] + a1[2 * q]) * inv + bx + rr.x;
        float oy = (a0[2 * q + 1] + a1[2 * q + 1]) * inv + by + rr.y;
        if (RELU) { ox = fmaxf(ox, 0.f); oy = fmaxf(oy, 0.f); }
        ow[q] = h2u(ox, oy);
    }
    if (HL == 8)
        __stcs(reinterpret_cast<uint4*>(&outp[(size_t)n * F + fo]), *reinterpret_cast<uint4*>(ow));
    else
        __stcs(reinterpret_cast<uint2*>(&outp[(size_t)n * F + fo]), *reinterpret_cast<uint2*>(ow));
}

// ---------------- edge decoder (CSR-grouped; 8 edges in flight per warp) -----
__global__ void k_edge_csr(const __half* __restrict__ u_, const __half* __restrict__ v_,
                           const float* __restrict__ bd1, const float* __restrict__ wd2,
                           const float* __restrict__ bd2, float* __restrict__ out) {
    int warp = (blockIdx.x * blockDim.x + threadIdx.x) >> 5;
    int lane = threadIdx.x & 31;
    if (warp >= NN) return;
    const int n = warp;
    int beg = g_off[n];
    int c = g_cnt[n];
    if (c == 0) return;

    const int sub = lane >> 3;   // edge slot 0..3
    const int fl = lane & 7;     // feature block: cols fl*16 .. fl*16+15

    float w16[16], vb16[16];
#pragma unroll
    for (int q = 0; q < 4; q++) {
        float4 wv = *reinterpret_cast<const float4*>(&wd2[fl * 16 + q * 4]);
        w16[4 * q + 0] = wv.x; w16[4 * q + 1] = wv.y;
        w16[4 * q + 2] = wv.z; w16[4 * q + 3] = wv.w;
        float4 bv = *reinterpret_cast<const float4*>(&bd1[fl * 16 + q * 4]);
        vb16[4 * q + 0] = bv.x; vb16[4 * q + 1] = bv.y;
        vb16[4 * q + 2] = bv.z; vb16[4 * q + 3] = bv.w;
    }
    {
        uint4 vv0 = __ldcs(reinterpret_cast<const uint4*>(&v_[(size_t)n * 128 + fl * 16]));
        uint4 vv1 = __ldcs(reinterpret_cast<const uint4*>(&v_[(size_t)n * 128 + fl * 16 + 8]));
        uint32_t vw[8] = {vv0.x, vv0.y, vv0.z, vv0.w, vv1.x, vv1.y, vv1.z, vv1.w};
#pragma unroll
        for (int q = 0; q < 8; q++) {
            float2 f = u2f(vw[q]);
            vb16[2 * q] += f.x;
            vb16[2 * q + 1] += f.y;
        }
    }
    float b2 = *bd2;

    auto edge_dot = [&](int idx) -> float {
        int s = g_src[idx];
        uint4 uu0 = *reinterpret_cast<const uint4*>(&u_[(size_t)s * 128 + fl * 16]);
        uint4 uu1 = *reinterpret_cast<const uint4*>(&u_[(size_t)s * 128 + fl * 16 + 8]);
        uint32_t uw[8] = {uu0.x, uu0.y, uu0.z, uu0.w, uu1.x, uu1.y, uu1.z, uu1.w};
        float sum = 0.f;
#pragma unroll
        for (int q = 0; q < 8; q++) {
            float2 f = u2f(uw[q]);
            float t;
            t = fmaxf(f.x + vb16[2 * q], 0.f);     sum = fmaf(t, w16[2 * q], sum);
            t = fmaxf(f.y + vb16[2 * q + 1], 0.f); sum = fmaf(t, w16[2 * q + 1], sum);
        }
        sum += __shfl_xor_sync(0xFFFFFFFFu, sum, 4);
        sum += __shfl_xor_sync(0xFFFFFFFFu, sum, 2);
        sum += __shfl_xor_sync(0xFFFFFFFFu, sum, 1);
        return sum;
    };

    int i = 0;
    for (; i + 8 <= c; i += 8) {
        int idxA = beg + i + sub, idxB = beg + i + 4 + sub;
        int eidA = g_eid[idxA], eidB = g_eid[idxB];
        float sA = edge_dot(idxA);
        float sB = edge_dot(idxB);
        if (fl == 0) {
            __stcs(&out[eidA], sA + b2);
            __stcs(&out[eidB], sB + b2);
        }
    }
    for (; i < c; i += 4) {
        int j = i + sub;
        bool ok = (j < c);
        int idx = beg + (ok ? j : c - 1);
        int eid = g_eid[idx];
        float s = edge_dot(idx);
        if (fl == 0 && ok) __stcs(&out[eid], s + b2);
    }
}

// ---------------- launch -----------------------------------------------------
extern "C" void kernel_launch(void* const* d_in, const int* in_sizes, int n_in,
                              void* d_out, int out_size) {
    const float* x       = (const float*)d_in[0];
    const void*  ei      = (const void*)d_in[1];
    const float* W1l     = (const float*)d_in[2];
    const float* b1l     = (const float*)d_in[3];
    const float* W1r     = (const float*)d_in[4];
    const float* W2l     = (const float*)d_in[5];
    const float* b2l     = (const float*)d_in[6];
    const float* W2r     = (const float*)d_in[7];
    const float* Wd1     = (const float*)d_in[8];
    const float* bd1     = (const float*)d_in[9];
    const float* Wd2     = (const float*)d_in[10];
    const float* bd2     = (const float*)d_in[11];
    float* out           = (float*)d_out;

    __half *yh, *rh, *hh, *zh, *w1, *w2, *wd;
    cudaGetSymbolAddress((void**)&yh, g_yh);
    cudaGetSymbolAddress((void**)&rh, g_rh);
    cudaGetSymbolAddress((void**)&hh, g_hh);
    cudaGetSymbolAddress((void**)&zh, g_zh);
    cudaGetSymbolAddress((void**)&w1, g_w1);
    cudaGetSymbolAddress((void**)&w2, g_w2);
    cudaGetSymbolAddress((void**)&wd, g_wd);

    const int smemK256 = (256 * (256 / 2 + 4) + 4 * 128 * 20) * 4;  // 176128
    const int smemK128 = (256 * (128 / 2 + 4) + 4 * 128 * 20) * 4;  // 110592
    cudaFuncSetAttribute(k_gemm_mma<256, 4, false>, cudaFuncAttributeMaxDynamicSharedMemorySize, smemK256);
    cudaFuncSetAttribute(k_gemm_mma<256, 2, true>,  cudaFuncAttributeMaxDynamicSharedMemorySize, smemK256);
    cudaFuncSetAttribute(k_gemm_mma<128, 2, true>,  cudaFuncAttributeMaxDynamicSharedMemorySize, smemK128);

    const int MT2 = (NN + 255) / 256;             // 391 CTAs (256 rows each)
    const int AGG_GRID = (NN * 32 + 255) / 256;   // warp per node

    // ---- fork: CSR build on side stream, weights+GEMM1 on main stream ----
    cudaStream_t s2 = g_ss.s;
    cudaEventRecord(g_ss.fork, 0);
    cudaStreamWaitEvent(s2, g_ss.fork, 0);

    k_detect<<<1, 32, 0, s2>>>((const int*)ei);
    k_zero_cnt<<<(NN + 255) / 256, 256, 0, s2>>>();
    k_cvt_hist<<<(NE + 255) / 256, 256, 0, s2>>>(ei);
    k_scanA<<<SCAN_B, 256, 0, s2>>>();
    k_scanB<<<1, 512, 0, s2>>>();
    k_scanC<<<SCAN_B, 256, 0, s2>>>();
    k_scatter<<<(NE + 255) / 256, 256, 0, s2>>>();
    cudaEventRecord(g_ss.join, s2);

    // main stream: convert weights (tiny), then conv1 GEMM
    k_cvtW<<<(512 * 256 + 256 * 256 + 256 * 128 + 255) / 256, 256>>>(W1l, W1r, W2l, W2r, Wd1);
    k_gemm_mma<256, 4, false><<<MT2, 256, smemK256>>>(x, w1, yh, rh, NN, 256);

    // join: agg needs CSR + GEMM1
    cudaStreamWaitEvent(0, g_ss.join, 0);

    // conv1 aggregation -> h (fp16)
    k_agg_h<8, true><<<AGG_GRID, 256>>>(yh, rh, b1l, hh);

    // conv2 (A = h fp16)
    k_gemm_mma<256, 2, true><<<MT2, 256, smemK256>>>(hh, w2, yh, rh, NN, 128);
    k_agg_h<4, false><<<AGG_GRID, 256>>>(yh, rh, b2l, zh);

    // decoder precompute: u = z@A^T, v = z@B^T (A = z fp16)
    k_gemm_mma<128, 2, true><<<MT2, 256, smemK128>>>(zh, wd, yh, rh, NN, 128);

    // per-edge (CSR-grouped): out = Wd2 . relu(u[src]+v[dst]+bd1) + bd2
    k_edge_csr<<<AGG_GRID, 256>>>(yh, rh, bd1, Wd2, bd2, out);
}